// round 15
// baseline (speedup 1.0000x reference)
#include <cuda_runtime.h>
#include <cuda_bf16.h>
#include <cuda_fp16.h>
#include <math.h>
#include <stdint.h>

// ---------------------------------------------------------------------------
// Problem constants
// ---------------------------------------------------------------------------
#define B_    256
#define K_    4
#define CIN_  256
#define CV_   128
#define COUT_ 256
#define HW_   256      // 16*16
#define LOG2PI 1.8378770664093453f

// Output layout (concatenated flat float32)
#define OFF_OUT 0
#define OFF_Z   16777216
#define OFF_LPP 25165824
#define OFF_LPQ 58720256
#define OFF_KLT 67108864
#define OFF_QMU 67108865   // ODD -> never access as float4!
#define OFF_QLV 75497473   // ODD -> never access as float4!
#define OFF_Y   83886081
#define OFF_CE  83887105

// ---------------------------------------------------------------------------
// Scratch (device-global; no runtime allocation)
// ---------------------------------------------------------------------------
__device__ __align__(16) float  g_t1[B_ * 2 * CV_ * HW_];
__device__ __align__(16) float  g_logits[B_ * K_];
__device__ double g_kl_sum;
__device__ double g_js_mean;

// B tiles, LDS.128-friendly layout. Per (chunk,ctile) block: 5760 words
// (9 taps x 32 lanes x 20 words; per lane: 16 fragment words (nt*2+reg) + 4 pad).
#define BLK_WORDS 5760
#define WOFF_QY  0                    // 16*2 blocks
#define WOFF_QZ1 184320               // 16*4 blocks
#define WOFF_QZ2 552960               // 16*4 blocks
#define WOFF_OUT 921600               //  8*4 blocks
#define WBUF_TOTAL 1105920
__device__ __align__(16) uint32_t g_wbuf[WBUF_TOTAL];

// ---------------------------------------------------------------------------
// Helpers
// ---------------------------------------------------------------------------
__device__ __forceinline__ float clamp10(float v) {
    return fminf(fmaxf(v, -10.0f), 10.0f);
}
__device__ __forceinline__ float std_from_lv(float lv) {
    return (lv < 0.0f) ? expf(0.5f * lv) : (1.0f + lv);
}
__device__ __forceinline__ float logstd_from_lv(float lv) {
    return (lv < 0.0f) ? 0.5f * lv : log1pf(lv);
}
__device__ __forceinline__ uint32_t smem_u32(const void* p) {
    return (uint32_t)__cvta_generic_to_shared(p);
}
__device__ __forceinline__ uint32_t pack_h2(__half a, __half b) {
    return (uint32_t)__half_as_ushort(a) | ((uint32_t)__half_as_ushort(b) << 16);
}
__device__ __forceinline__ void ldsm4(uint32_t r[4], uint32_t addr) {
    asm volatile("ldmatrix.sync.aligned.m8n8.x4.shared.b16 {%0,%1,%2,%3}, [%4];"
                 : "=r"(r[0]), "=r"(r[1]), "=r"(r[2]), "=r"(r[3]) : "r"(addr));
}
__device__ __forceinline__ void mma16816(float c[4], const uint32_t a[4], uint32_t b0, uint32_t b1) {
    asm volatile(
        "mma.sync.aligned.m16n8k16.row.col.f32.f16.f16.f32 "
        "{%0,%1,%2,%3}, {%4,%5,%6,%7}, {%8,%9}, {%0,%1,%2,%3};"
        : "+f"(c[0]), "+f"(c[1]), "+f"(c[2]), "+f"(c[3])
        : "r"(a[0]), "r"(a[1]), "r"(a[2]), "r"(a[3]), "r"(b0), "r"(b1));
}
__device__ __forceinline__ void cp_async16(uint32_t saddr, const void* g) {
    asm volatile("cp.async.cg.shared.global [%0], [%1], 16;" :: "r"(saddr), "l"(g));
}

// ---------------------------------------------------------------------------
// logits init: logits[b,k] = qy_lin_b[k]
// ---------------------------------------------------------------------------
__global__ void logits_init_kernel(const float* __restrict__ lb, float* __restrict__ logits) {
    int t = threadIdx.x;   // 1024 threads
    logits[t] = lb[t & 3];
}

// ---------------------------------------------------------------------------
// Weight prep (range [base, base+count) of g_wbuf):
// word at WOFF + blk*5760 + t*640 + lane*20 + (nt*2+reg); words 16..19 pad=0.
// pair-mode (qz2): co = ctile*32 + (nt&3)*8 + g + (nt>=4 ? 128 : 0)
// ---------------------------------------------------------------------------
__global__ void wprep_kernel(const float* __restrict__ qyw,
                             const float* __restrict__ qz1w,
                             const float* __restrict__ qz2w,
                             const float* __restrict__ outw,
                             uint32_t* __restrict__ dst, int base, int count) {
    int gid = blockIdx.x * 256 + threadIdx.x;
    if (gid >= count) return;
    int idx = base + gid;
    const float* w;
    int CIN, CTILES, pair, rel;
    if (idx < WOFF_QZ1)      { w = qyw;  CIN = 256; CTILES = 2; pair = 0; rel = idx; }
    else if (idx < WOFF_QZ2) { w = qz1w; CIN = 256; CTILES = 4; pair = 0; rel = idx - WOFF_QZ1; }
    else if (idx < WOFF_OUT) { w = qz2w; CIN = 256; CTILES = 4; pair = 1; rel = idx - WOFF_QZ2; }
    else                     { w = outw; CIN = 128; CTILES = 4; pair = 0; rel = idx - WOFF_OUT; }
    int blk = rel / BLK_WORDS;
    int w2 = rel - blk * BLK_WORDS;
    int chunk = blk / CTILES;
    int ctile = blk - chunk * CTILES;
    int t = w2 / 640;
    int r = w2 - t * 640;
    int lane = r / 20;
    int o = r - lane * 20;
    uint32_t val = 0;
    if (o < 16) {
        int nt = o >> 1, reg = o & 1;
        int i = lane & 3, g = lane >> 2;
        int ci = chunk * 16 + 2 * i + 8 * reg;
        int co = pair ? (ctile * 32 + (nt & 3) * 8 + g + ((nt >= 4) ? 128 : 0))
                      : (ctile * 64 + nt * 8 + g);
        float f0 = w[(co * CIN + ci) * 9 + t];
        float f1 = w[(co * CIN + ci + 1) * 9 + t];
        val = pack_h2(__float2half_rn(f0), __float2half_rn(f1));
    }
    dst[idx] = val;
}

// ---------------------------------------------------------------------------
// Implicit-GEMM 3x3 conv via mma.sync, fp16 A hi/lo split x fp16 B.
// Single-sync pipelined mainloop (s_a + s_b double-buffered; B via cp.async;
// A raw fp32 register-prefetched). B fragments loaded as 4x LDS.128 per tap.
// AFFINE: gamma/beta computed inline from logits (no gb kernel).
// Block: 256 threads (8 warps). Tile: 1 image x 64 couts x 256 pixels.
// SMEM: s_a 2x20560 + s_b 2x23040 = 87200 B -> 2 CTAs/SM
// ---------------------------------------------------------------------------
#define SA_STRIDE  20560
#define SB_OFF     41120
#define CONV_SMEM  87200

template <int CIN, int COUT, bool RELU, bool AFFINE, bool PAIRZ, bool QYFUSE>
__global__ __launch_bounds__(256, 2)
void conv_mma_kernel(const float* __restrict__ in, const uint32_t* __restrict__ wbuf,
                     const float* __restrict__ bias, float* __restrict__ out,
                     const float* __restrict__ gw, const float* __restrict__ gb,
                     const float* __restrict__ bw, const float* __restrict__ bb,
                     const float* __restrict__ wlin, float* __restrict__ logits,
                     const float* __restrict__ eps) {
    extern __shared__ char smem[];
    char* s_a = smem;                                    // 2 x (257 rows * 80 B)
    uint32_t* s_b = (uint32_t*)(smem + SB_OFF);          // 2 x 5760 words
    constexpr int CHUNKS = CIN / 16;
    constexpr int CTILES = COUT / 64;

    const int tid = threadIdx.x;
    const int lane = tid & 31;
    const int warp = tid >> 5;
    const int ctile = blockIdx.x;
    const int b = blockIdx.y;
    const int cout0 = ctile * 64;

    const uint32_t sa_base = smem_u32(s_a);

    // zero OOB row (row 256) of both A buffers
    if (tid < 40) {
        int buf = tid / 20, w = tid % 20;
        *(uint32_t*)(s_a + buf * SA_STRIDE + 256 * 80 + w * 4) = 0;
    }

    // AFFINE: logits for this image
    float l0 = 0.f, l1 = 0.f, l2 = 0.f, l3 = 0.f;
    if (AFFINE) {
        l0 = logits[b * 4 + 0];
        l1 = logits[b * 4 + 1];
        l2 = logits[b * 4 + 2];
        l3 = logits[b * 4 + 3];
    }

    float acc[2][8][4];
#pragma unroll
    for (int mt = 0; mt < 2; mt++)
#pragma unroll
        for (int nt = 0; nt < 8; nt++)
#pragma unroll
            for (int j = 0; j < 4; j++) acc[mt][nt][j] = 0.0f;

    const int rowsel = lane & 15;
    const int khalf = lane >> 4;

    const float* inbase = in + (((size_t)b * CIN) << 8);

    // convert-and-store one channel pair into buffer
    auto convert_pair = [&](char* sa, int cglob, int ci, float v0, float v1) {
        if (AFFINE) {
            float4 g40 = ((const float4*)gw)[cglob];
            float4 b40 = ((const float4*)bw)[cglob];
            float4 g41 = ((const float4*)gw)[cglob + 1];
            float4 b41 = ((const float4*)bw)[cglob + 1];
            float ga0 = g40.x * l0 + g40.y * l1 + g40.z * l2 + g40.w * l3 + gb[cglob];
            float be0 = b40.x * l0 + b40.y * l1 + b40.z * l2 + b40.w * l3 + bb[cglob];
            float ga1 = g41.x * l0 + g41.y * l1 + g41.z * l2 + g41.w * l3 + gb[cglob + 1];
            float be1 = b41.x * l0 + b41.y * l1 + b41.z * l2 + b41.w * l3 + bb[cglob + 1];
            v0 = ga0 * v0 + be0;
            v1 = ga1 * v1 + be1;
        }
        __half h0 = __float2half_rn(v0), h1 = __float2half_rn(v1);
        __half lo0 = __float2half_rn(v0 - __half2float(h0));
        __half lo1 = __float2half_rn(v1 - __half2float(h1));
        *(uint32_t*)(sa + tid * 80 + ci * 2) = pack_h2(h0, h1);
        *(uint32_t*)(sa + tid * 80 + 32 + ci * 2) = pack_h2(lo0, lo1);
    };

    float areg[16];
    // ---- prologue: A(0) -> regs -> convert into s_a[0]; B(0) via cp.async ----
#pragma unroll
    for (int ci = 0; ci < 16; ci++) areg[ci] = inbase[(ci << 8) + tid];
    {
        const uint4* srcB = (const uint4*)(wbuf + (size_t)(0 * CTILES + ctile) * BLK_WORDS);
        uint32_t db = smem_u32(s_b);
        for (int i = tid; i < 1440; i += 256) cp_async16(db + i * 16, srcB + i);
        asm volatile("cp.async.commit_group;");
    }
#pragma unroll
    for (int ci = 0; ci < 16; ci += 2)
        convert_pair(s_a, ci, ci, areg[ci], areg[ci + 1]);
    if (CHUNKS > 1) {
        const float* inp = inbase + (16 << 8);
#pragma unroll
        for (int ci = 0; ci < 16; ci++) areg[ci] = inp[(ci << 8) + tid];
    }
    asm volatile("cp.async.wait_group 0;");
    __syncthreads();

    for (int ch = 0; ch < CHUNKS; ch++) {
        const int cur = ch & 1;
        const int nxt = cur ^ 1;

        // ---- issue B prefetch for ch+1 ----
        if (ch + 1 < CHUNKS) {
            const uint4* srcB = (const uint4*)(wbuf + (size_t)((ch + 1) * CTILES + ctile) * BLK_WORDS);
            uint32_t db = smem_u32(s_b + nxt * BLK_WORDS);
            for (int i = tid; i < 1440; i += 256) cp_async16(db + i * 16, srcB + i);
            asm volatile("cp.async.commit_group;");
        }

        // ---- compute chunk ch from buffers[cur] ----
        const uint32_t sab = sa_base + cur * SA_STRIDE;
        const uint32_t* sb = s_b + cur * BLK_WORDS;
#pragma unroll
        for (int dy = 0; dy < 3; dy++) {
#pragma unroll
            for (int dx = 0; dx < 3; dx++) {
                const int t = dy * 3 + dx;
                const uint32_t* sbt = sb + t * 640 + lane * 20;
                uint4 q0 = *(const uint4*)(sbt + 0);
                uint4 q1 = *(const uint4*)(sbt + 4);
                uint4 q2 = *(const uint4*)(sbt + 8);
                uint4 q3 = *(const uint4*)(sbt + 12);
                uint32_t bf[16] = {q0.x, q0.y, q0.z, q0.w, q1.x, q1.y, q1.z, q1.w,
                                   q2.x, q2.y, q2.z, q2.w, q3.x, q3.y, q3.z, q3.w};
                const int sx = rowsel + dx - 1;
                const bool colok = (unsigned)sx < 16u;
#pragma unroll
                for (int mt = 0; mt < 2; mt++) {
                    const int y = warp * 2 + mt;
                    const int sy = y + dy - 1;
                    const bool ok = colok && ((unsigned)sy < 16u);
                    const int spix = ok ? (sy * 16 + sx) : 256;
                    const uint32_t addr = sab + (uint32_t)spix * 80u + (uint32_t)khalf * 16u;
                    uint32_t ah[4], al[4];
                    ldsm4(ah, addr);
                    ldsm4(al, addr + 32u);
#pragma unroll
                    for (int nt = 0; nt < 8; nt++) {
                        mma16816(acc[mt][nt], ah, bf[nt * 2], bf[nt * 2 + 1]);
                        mma16816(acc[mt][nt], al, bf[nt * 2], bf[nt * 2 + 1]);
                    }
                }
            }
        }

        // ---- convert A(ch+1) into s_a[nxt]; refill areg with A(ch+2) ----
        if (ch + 1 < CHUNKS) {
            char* san = s_a + nxt * SA_STRIDE;
#pragma unroll
            for (int ci = 0; ci < 16; ci += 2)
                convert_pair(san, (ch + 1) * 16 + ci, ci, areg[ci], areg[ci + 1]);
            if (ch + 2 < CHUNKS) {
                const float* inp = inbase + ((size_t)(ch + 2) * 16 << 8);
#pragma unroll
                for (int ci = 0; ci < 16; ci++) areg[ci] = inp[(ci << 8) + tid];
            }
            asm volatile("cp.async.wait_group 0;");
        }
        __syncthreads();
    }

    const int g = lane >> 2;
    const int i2 = (lane & 3) * 2;

    if constexpr (QYFUSE) {
        // h = relu(conv+bias); logits_k += sum h * wlin[k]. h never stored.
        float a[4] = {0.f, 0.f, 0.f, 0.f};
#pragma unroll
        for (int nt = 0; nt < 8; nt++) {
            const int co = cout0 + nt * 8 + i2;
            const float bz0 = bias[co];
            const float bz1 = bias[co + 1];
#pragma unroll
            for (int mt = 0; mt < 2; mt++) {
                const int pixa = warp * 32 + mt * 16 + g;
                float v0 = fmaxf(acc[mt][nt][0] + bz0, 0.0f);
                float v1 = fmaxf(acc[mt][nt][1] + bz1, 0.0f);
                float v2 = fmaxf(acc[mt][nt][2] + bz0, 0.0f);
                float v3 = fmaxf(acc[mt][nt][3] + bz1, 0.0f);
#pragma unroll
                for (int k = 0; k < 4; k++) {
                    const float* wk = wlin + (size_t)k * 32768;
                    a[k] += v0 * wk[co * 256 + pixa] + v1 * wk[(co + 1) * 256 + pixa]
                          + v2 * wk[co * 256 + pixa + 8] + v3 * wk[(co + 1) * 256 + pixa + 8];
                }
            }
        }
        float* red = (float*)smem;
        __syncthreads();
#pragma unroll
        for (int k = 0; k < 4; k++) {
            red[tid] = a[k];
            __syncthreads();
            for (int s = 128; s > 0; s >>= 1) {
                if (tid < s) red[tid] += red[tid + s];
                __syncthreads();
            }
            if (tid == 0) atomicAdd(&logits[b * 4 + k], red[0]);
            __syncthreads();
        }
    } else if constexpr (PAIRZ) {
        // qz2 epilogue fused with z: nt<4 = mu channels, nt+4 = lv channels.
        const int base_c = ctile * 32;
#pragma unroll
        for (int nt = 0; nt < 4; nt++) {
#pragma unroll
            for (int mt = 0; mt < 2; mt++) {
#pragma unroll
                for (int j = 0; j < 4; j++) {
                    const int c = base_c + nt * 8 + i2 + (j & 1);
                    const int pix = warp * 32 + mt * 16 + g + ((j >> 1) << 3);
                    float mu = clamp10(acc[mt][nt][j] + bias[c]);
                    float lv = clamp10(acc[mt][nt + 4][j] + bias[c + 128]);
                    float sd = std_from_lv(lv);
                    float lsd = logstd_from_lv(lv);
                    size_t idx = (((size_t)b * 128 + c) << 8) + pix;
                    float e = eps[idx];
                    out[OFF_Z + idx] = mu + sd * e;
                    out[OFF_QMU + idx] = mu;
                    out[OFF_QLV + idx] = lv;
                    out[OFF_LPQ + idx] = -0.5f * e * e - lsd - 0.5f * LOG2PI;
                }
            }
        }
    } else {
        // normal epilogue
#pragma unroll
        for (int nt = 0; nt < 8; nt++) {
            const int co = cout0 + nt * 8 + i2;
            const float bz0 = bias[co];
            const float bz1 = bias[co + 1];
            float* o = out + (((size_t)b * COUT + co) << 8);
#pragma unroll
            for (int mt = 0; mt < 2; mt++) {
                const int pixa = warp * 32 + mt * 16 + g;
                float v0 = acc[mt][nt][0] + bz0;
                float v1 = acc[mt][nt][1] + bz1;
                float v2 = acc[mt][nt][2] + bz0;
                float v3 = acc[mt][nt][3] + bz1;
                if (RELU) {
                    v0 = fmaxf(v0, 0.0f); v1 = fmaxf(v1, 0.0f);
                    v2 = fmaxf(v2, 0.0f); v3 = fmaxf(v3, 0.0f);
                }
                o[pixa] = v0;
                o[256 + pixa] = v1;
                o[pixa + 8] = v2;
                o[256 + pixa + 8] = v3;
            }
        }
    }
}

// ---------------------------------------------------------------------------
// Per-batch small work: gumbel softmax y, cross_entropy, js.
// ---------------------------------------------------------------------------
__global__ __launch_bounds__(256)
void small_kernel(const float* __restrict__ logits, const float* __restrict__ u,
                  const int* __restrict__ label, float* __restrict__ out) {
    const int b = threadIdx.x;
    float l[K_], y[K_];
#pragma unroll
    for (int k = 0; k < K_; k++) l[k] = logits[b * K_ + k];

    float s[K_];
    float mx = -1e30f;
#pragma unroll
    for (int k = 0; k < K_; k++) {
        float uu = u[b * K_ + k];
        float g = -logf(-logf(uu));
        s[k] = l[k] + g;
        mx = fmaxf(mx, s[k]);
    }
    float sum = 0.0f;
#pragma unroll
    for (int k = 0; k < K_; k++) { y[k] = expf(s[k] - mx); sum += y[k]; }
    float inv = 1.0f / sum;
#pragma unroll
    for (int k = 0; k < K_; k++) {
        y[k] *= inv;
        out[OFF_Y + b * K_ + k] = y[k];
    }

    float mx2 = fmaxf(fmaxf(l[0], l[1]), fmaxf(l[2], l[3]));
    float se = 0.0f;
#pragma unroll
    for (int k = 0; k < K_; k++) se += expf(l[k] - mx2);
    float lse = logf(se) + mx2;
    int lbl = label[b];
    float ce_b = lse - l[lbl];

    const float prior = 1.0f / K_;
    float t1 = 0.0f, t2 = 0.0f;
#pragma unroll
    for (int k = 0; k < K_; k++) {
        float m = 0.5f * (y[k] + prior);
        t1 += y[k] * logf(y[k] / (m + 1e-10f));
        t2 += prior * logf(prior / (m + 1e-10f));
    }
    float js_b = 0.5f * t1 + 0.5f * t2;

    __shared__ double r1[256], r2[256];
    r1[b] = (double)ce_b;
    r2[b] = (double)js_b;
    __syncthreads();
    for (int st = 128; st > 0; st >>= 1) {
        if (b < st) { r1[b] += r1[b + st]; r2[b] += r2[b + st]; }
        __syncthreads();
    }
    if (b == 0) {
        out[OFF_CE] = (float)(r1[0] / (double)B_);
        g_js_mean = r2[0] / (double)B_;
        g_kl_sum = 0.0;
    }
}

// ---------------------------------------------------------------------------
// logprob_p (layout [b,c,pix,k]) + fused KL(label) reduce (float4 over pix)
// ---------------------------------------------------------------------------
__global__ __launch_bounds__(256)
void pk_kernel(const float* __restrict__ p, const int* __restrict__ label,
               float* __restrict__ out) {
    int idx = blockIdx.x * 256 + threadIdx.x;   // B*CV*HW/4
    int e4 = idx << 2;
    int b = e4 >> 15;
    int r = e4 & 32767;
    int c = r >> 8;
    int pix = r & 255;
    int lbl = label[b];

    float4 z4 = ((const float4*)(out + OFF_Z))[idx];
    float zz[4] = {z4.x, z4.y, z4.z, z4.w};
    float qm[4], qs[4], lqs[4];
    const float* qmu = out + OFF_QMU + e4;
    const float* qlvp = out + OFF_QLV + e4;
#pragma unroll
    for (int j = 0; j < 4; j++) {
        qm[j] = qmu[j];
        float qlv = qlvp[j];
        qs[j] = std_from_lv(qlv);
        lqs[j] = logstd_from_lv(qlv);
    }

    float lp[4][4];
    float klv = 0.0f;
#pragma unroll
    for (int k = 0; k < K_; k++) {
        size_t base = (((size_t)b * (2 * K_ * CV_) + k * CV_ + c) << 8) + pix;
        float4 pm4 = *(const float4*)&p[base];
        float4 pl4 = *(const float4*)&p[base + ((size_t)(K_ * CV_) << 8)];
        float pmv[4] = {pm4.x, pm4.y, pm4.z, pm4.w};
        float plv[4] = {pl4.x, pl4.y, pl4.z, pl4.w};
#pragma unroll
        for (int j = 0; j < 4; j++) {
            float pm = clamp10(pmv[j]);
            float pv = clamp10(plv[j]);
            float ps = std_from_lv(pv);
            float lps = logstd_from_lv(pv);
            float inv_ps = 1.0f / ps;
            float d = (zz[j] - pm) * inv_ps;
            lp[j][k] = -0.5f * d * d - lps - 0.5f * LOG2PI;
            if (k == lbl) {
                float dd = qm[j] - pm;
                klv += lps - lqs[j] +
                       (qs[j] * qs[j] + dd * dd) * (0.5f * inv_ps * inv_ps) - 0.5f;
            }
        }
    }
    float4* lpp = (float4*)(out + OFF_LPP) + (size_t)e4;
#pragma unroll
    for (int j = 0; j < 4; j++)
        lpp[j] = make_float4(lp[j][0], lp[j][1], lp[j][2], lp[j][3]);

    __shared__ float red[256];
    red[threadIdx.x] = klv;
    __syncthreads();
    for (int s = 128; s > 0; s >>= 1) {
        if (threadIdx.x < s) red[threadIdx.x] += red[threadIdx.x + s];
        __syncthreads();
    }
    if (threadIdx.x == 0) atomicAdd(&g_kl_sum, (double)red[0]);
}

__global__ void finalize_kernel(float* __restrict__ out) {
    out[OFF_KLT] = (float)(g_kl_sum / (double)(B_ * CV_ * HW_) + g_js_mean);
}

// ---------------------------------------------------------------------------
// Launch
// ---------------------------------------------------------------------------
extern "C" void kernel_launch(void* const* d_in, const int* in_sizes, int n_in,
                              void* d_out, int out_size) {
    const float* p_params = (const float*)d_in[0];
    const float* q_params = (const float*)d_in[1];
    const int*   label    = (const int*)d_in[2];
    const float* eps      = (const float*)d_in[3];
    const float* u_gumbel = (const float*)d_in[4];
    const float* qy_conv_w = (const float*)d_in[5];
    const float* qy_conv_b = (const float*)d_in[6];
    const float* qy_lin_w  = (const float*)d_in[7];
    const float* qy_lin_b  = (const float*)d_in[8];
    const float* gamma_w   = (const float*)d_in[9];
    const float* gamma_b   = (const float*)d_in[10];
    const float* beta_w    = (const float*)d_in[11];
    const float* beta_b    = (const float*)d_in[12];
    const float* qz1_w     = (const float*)d_in[13];
    const float* qz1_b     = (const float*)d_in[14];
    const float* qz2_w     = (const float*)d_in[15];
    const float* qz2_b     = (const float*)d_in[16];
    const float* out_w     = (const float*)d_in[17];
    const float* out_b     = (const float*)d_in[18];
    float* out = (float*)d_out;

    float *t1, *logits;
    uint32_t* wbuf;
    cudaGetSymbolAddress((void**)&t1, g_t1);
    cudaGetSymbolAddress((void**)&logits, g_logits);
    cudaGetSymbolAddress((void**)&wbuf, g_wbuf);

    cudaFuncSetAttribute(conv_mma_kernel<CIN_, CV_, true, false, false, true>,
                         cudaFuncAttributeMaxDynamicSharedMemorySize, CONV_SMEM);
    cudaFuncSetAttribute(conv_mma_kernel<CIN_, 2 * CV_, true, true, false, false>,
                         cudaFuncAttributeMaxDynamicSharedMemorySize, CONV_SMEM);
    cudaFuncSetAttribute(conv_mma_kernel<2 * CV_, 2 * CV_, false, false, true, false>,
                         cudaFuncAttributeMaxDynamicSharedMemorySize, CONV_SMEM);
    cudaFuncSetAttribute(conv_mma_kernel<CV_, COUT_, false, false, false, false>,
                         cudaFuncAttributeMaxDynamicSharedMemorySize, CONV_SMEM);

    cudaStream_t s2;
    cudaStreamCreateWithFlags(&s2, cudaStreamNonBlocking);
    cudaEvent_t evA, evW, evB, evC, evD;
    cudaEventCreateWithFlags(&evA, cudaEventDisableTiming);
    cudaEventCreateWithFlags(&evW, cudaEventDisableTiming);
    cudaEventCreateWithFlags(&evB, cudaEventDisableTiming);
    cudaEventCreateWithFlags(&evC, cudaEventDisableTiming);
    cudaEventCreateWithFlags(&evD, cudaEventDisableTiming);

    // main: logits init + qy weight prep
    logits_init_kernel<<<1, 1024>>>(qy_lin_b, logits);
    wprep_kernel<<<(WOFF_QZ1 + 255) / 256, 256>>>(
        qy_conv_w, qz1_w, qz2_w, out_w, wbuf, 0, WOFF_QZ1);
    cudaEventRecord(evA, 0);
    // s2: rest of weight prep (runs under qy conv)
    cudaStreamWaitEvent(s2, evA, 0);
    wprep_kernel<<<((WBUF_TOTAL - WOFF_QZ1) + 255) / 256, 256, 0, s2>>>(
        qy_conv_w, qz1_w, qz2_w, out_w, wbuf, WOFF_QZ1, WBUF_TOTAL - WOFF_QZ1);
    cudaEventRecord(evW, s2);

    // 1) qy conv + fused qy_lin -> logits
    conv_mma_kernel<CIN_, CV_, true, false, false, true><<<dim3(2, B_), 256, CONV_SMEM>>>(
        q_params, wbuf + WOFF_QY, qy_conv_b, nullptr,
        nullptr, nullptr, nullptr, nullptr, qy_lin_w, logits, nullptr);
    cudaEventRecord(evB, 0);
    // s2: small (y/ce/js + kl reset), parallel with qz1
    cudaStreamWaitEvent(s2, evB, 0);
    small_kernel<<<1, 256, 0, s2>>>(logits, u_gumbel, label, out);

    // main: qz1 (needs rest of wbuf) with inline affine from logits
    cudaStreamWaitEvent(0, evW, 0);
    conv_mma_kernel<CIN_, 2 * CV_, true, true, false, false><<<dim3(4, B_), 256, CONV_SMEM>>>(
        q_params, wbuf + WOFF_QZ1, qz1_b, t1,
        gamma_w, gamma_b, beta_w, beta_b, nullptr, logits, nullptr);
    // qz2 + fused z epilogue
    conv_mma_kernel<2 * CV_, 2 * CV_, false, false, true, false><<<dim3(4, B_), 256, CONV_SMEM>>>(
        t1, wbuf + WOFF_QZ2, qz2_b, out,
        nullptr, nullptr, nullptr, nullptr, nullptr, nullptr, eps);
    cudaEventRecord(evC, 0);

    // s2: pk (after small in s2 order, after qz2 via evC) || main: out conv
    cudaStreamWaitEvent(s2, evC, 0);
    pk_kernel<<<(B_ * CV_ * HW_) / 1024, 256, 0, s2>>>(p_params, label, out);
    cudaEventRecord(evD, s2);
    conv_mma_kernel<CV_, COUT_, false, false, false, false><<<dim3(4, B_), 256, CONV_SMEM>>>(
        out + OFF_Z, wbuf + WOFF_OUT, out_b, out + OFF_OUT,
        nullptr, nullptr, nullptr, nullptr, nullptr, nullptr, nullptr);
    cudaStreamWaitEvent(0, evD, 0);

    // finalize
    finalize_kernel<<<1, 1>>>(out);

    cudaEventDestroy(evA);
    cudaEventDestroy(evW);
    cudaEventDestroy(evB);
    cudaEventDestroy(evC);
    cudaEventDestroy(evD);
    cudaStreamDestroy(s2);
}

// round 16
// speedup vs baseline: 1.6868x; 1.6868x over previous
#include <cuda_runtime.h>
#include <cuda_bf16.h>
#include <cuda_fp16.h>
#include <math.h>
#include <stdint.h>

// ---------------------------------------------------------------------------
// Problem constants
// ---------------------------------------------------------------------------
#define B_    256
#define K_    4
#define CIN_  256
#define CV_   128
#define COUT_ 256
#define HW_   256      // 16*16
#define LOG2PI 1.8378770664093453f

// Output layout (concatenated flat float32)
#define OFF_OUT 0
#define OFF_Z   16777216
#define OFF_LPP 25165824
#define OFF_LPQ 58720256
#define OFF_KLT 67108864
#define OFF_QMU 67108865   // ODD -> never access as float4!
#define OFF_QLV 75497473   // ODD -> never access as float4!
#define OFF_Y   83886081
#define OFF_CE  83887105

// ---------------------------------------------------------------------------
// Scratch (device-global; no runtime allocation)
// ---------------------------------------------------------------------------
__device__ __align__(16) float  g_t1[B_ * 2 * CV_ * HW_];
__device__ __align__(16) float  g_logits[B_ * K_];
__device__ __align__(16) float  g_gamma[B_ * CIN_];
__device__ __align__(16) float  g_beta[B_ * CIN_];
__device__ double g_kl_sum;
__device__ double g_js_mean;

// Fragment-ordered fp16 weights (R12 layout). Regions (words):
#define WOFF_QY  0
#define WOFF_QZ1 147456
#define WOFF_QZ2 442368
#define WOFF_OUT 737280
#define WBUF_TOTAL 884736
__device__ __align__(16) uint32_t g_wbuf[WBUF_TOTAL];

// ---------------------------------------------------------------------------
// Helpers
// ---------------------------------------------------------------------------
__device__ __forceinline__ float clamp10(float v) {
    return fminf(fmaxf(v, -10.0f), 10.0f);
}
__device__ __forceinline__ float std_from_lv(float lv) {
    return (lv < 0.0f) ? expf(0.5f * lv) : (1.0f + lv);
}
__device__ __forceinline__ float logstd_from_lv(float lv) {
    return (lv < 0.0f) ? 0.5f * lv : log1pf(lv);
}
__device__ __forceinline__ uint32_t smem_u32(const void* p) {
    return (uint32_t)__cvta_generic_to_shared(p);
}
__device__ __forceinline__ uint32_t pack_h2(__half a, __half b) {
    return (uint32_t)__half_as_ushort(a) | ((uint32_t)__half_as_ushort(b) << 16);
}
__device__ __forceinline__ void ldsm4(uint32_t r[4], uint32_t addr) {
    asm volatile("ldmatrix.sync.aligned.m8n8.x4.shared.b16 {%0,%1,%2,%3}, [%4];"
                 : "=r"(r[0]), "=r"(r[1]), "=r"(r[2]), "=r"(r[3]) : "r"(addr));
}
__device__ __forceinline__ void mma16816(float c[4], const uint32_t a[4], uint32_t b0, uint32_t b1) {
    asm volatile(
        "mma.sync.aligned.m16n8k16.row.col.f32.f16.f16.f32 "
        "{%0,%1,%2,%3}, {%4,%5,%6,%7}, {%8,%9}, {%0,%1,%2,%3};"
        : "+f"(c[0]), "+f"(c[1]), "+f"(c[2]), "+f"(c[3])
        : "r"(a[0]), "r"(a[1]), "r"(a[2]), "r"(a[3]), "r"(b0), "r"(b1));
}
__device__ __forceinline__ void cp_async16(uint32_t saddr, const void* g) {
    asm volatile("cp.async.cg.shared.global [%0], [%1], 16;" :: "r"(saddr), "l"(g));
}

// ---------------------------------------------------------------------------
// logits init: logits[b,k] = qy_lin_b[k]
// ---------------------------------------------------------------------------
__global__ void logits_init_kernel(const float* __restrict__ lb, float* __restrict__ logits) {
    int t = threadIdx.x;   // 1024 threads
    logits[t] = lb[t & 3];
}

// ---------------------------------------------------------------------------
// Merged weight prep (R12 layout): all 4 convs in one launch.
// slot s in [0,4608): s = ((t*8+nt)*32 + lane)*2 + reg
// word at WOFF + blk*4608 + (t*8+nt)*64 + lane*2 + reg
// pair-mode (qz2): co = ctile*32 + (nt&3)*8 + g + (nt>=4 ? 128 : 0)
// ---------------------------------------------------------------------------
__global__ void wprep_all_kernel(const float* __restrict__ qyw,
                                 const float* __restrict__ qz1w,
                                 const float* __restrict__ qz2w,
                                 const float* __restrict__ outw,
                                 uint32_t* __restrict__ dst) {
    int idx = blockIdx.x * 256 + threadIdx.x;
    if (idx >= WBUF_TOTAL) return;
    const float* w;
    int CIN, CTILES, pair, rel;
    if (idx < WOFF_QZ1)      { w = qyw;  CIN = 256; CTILES = 2; pair = 0; rel = idx; }
    else if (idx < WOFF_QZ2) { w = qz1w; CIN = 256; CTILES = 4; pair = 0; rel = idx - WOFF_QZ1; }
    else if (idx < WOFF_OUT) { w = qz2w; CIN = 256; CTILES = 4; pair = 1; rel = idx - WOFF_QZ2; }
    else                     { w = outw; CIN = 128; CTILES = 4; pair = 0; rel = idx - WOFF_OUT; }
    int s = rel % 4608;
    int blk = rel / 4608;
    int chunk = blk / CTILES;
    int ctile = blk % CTILES;
    int reg = s & 1;
    int lane = (s >> 1) & 31;
    int nt = (s >> 6) & 7;
    int t = s >> 9;
    int i = lane & 3, g = lane >> 2;
    int ci = chunk * 16 + 2 * i + 8 * reg;
    int co = pair ? (ctile * 32 + (nt & 3) * 8 + g + ((nt >= 4) ? 128 : 0))
                  : (ctile * 64 + nt * 8 + g);
    float f0 = w[(co * CIN + ci) * 9 + t];
    float f1 = w[(co * CIN + ci + 1) * 9 + t];
    dst[idx] = pack_h2(__float2half_rn(f0), __float2half_rn(f1));
}

// ---------------------------------------------------------------------------
// Implicit-GEMM 3x3 conv via mma.sync, single fp16 A x fp16 B (1 MMA/tap/nt).
// Single-sync pipelined mainloop (s_a + s_b double-buffered; B via cp.async;
// A raw fp32 register-prefetched; convert into idle buffer after compute).
// A row = 32B data @ 48B stride (16B-aligned rows; conflict-free ldmatrix).
// Block: 256 threads (8 warps). Tile: 1 image x 64 couts x 256 pixels.
// SMEM: s_a 2x12336 + s_b 2x18432 = 61536 B -> 2 CTAs/SM
// ---------------------------------------------------------------------------
#define SA_STRIDE  12336               // 257 rows * 48
#define SB_OFF     24672
#define CONV_SMEM  61536

template <int CIN, int COUT, bool RELU, bool AFFINE, bool PAIRZ, bool QYFUSE>
__global__ __launch_bounds__(256, 2)
void conv_mma_kernel(const float* __restrict__ in, const uint32_t* __restrict__ wbuf,
                     const float* __restrict__ bias, float* __restrict__ out,
                     const float* __restrict__ gamma, const float* __restrict__ beta,
                     const float* __restrict__ wlin, float* __restrict__ logits,
                     const float* __restrict__ eps) {
    extern __shared__ char smem[];
    char* s_a = smem;                                    // 2 x (257 rows * 48 B)
    uint32_t* s_b = (uint32_t*)(smem + SB_OFF);          // 2 x 4608 words
    constexpr int CHUNKS = CIN / 16;
    constexpr int CTILES = COUT / 64;

    const int tid = threadIdx.x;
    const int lane = tid & 31;
    const int warp = tid >> 5;
    const int ctile = blockIdx.x;
    const int b = blockIdx.y;
    const int cout0 = ctile * 64;

    const uint32_t sa_base = smem_u32(s_a);

    // zero OOB row (row 256) of both A buffers (12 words each)
    if (tid < 24) {
        int buf = tid / 12, w = tid % 12;
        *(uint32_t*)(s_a + buf * SA_STRIDE + 256 * 48 + w * 4) = 0;
    }

    float acc[2][8][4];
#pragma unroll
    for (int mt = 0; mt < 2; mt++)
#pragma unroll
        for (int nt = 0; nt < 8; nt++)
#pragma unroll
            for (int j = 0; j < 4; j++) acc[mt][nt][j] = 0.0f;

    const int rowsel = lane & 15;
    const int khalf = lane >> 4;

    const float* inbase = in + (((size_t)b * CIN) << 8);

    float areg[16];
    // ---- prologue: A(0) -> regs -> convert into s_a[0]; B(0) via cp.async ----
#pragma unroll
    for (int ci = 0; ci < 16; ci++) areg[ci] = inbase[(ci << 8) + tid];
    {
        const uint4* srcB = (const uint4*)(wbuf + (size_t)(0 * CTILES + ctile) * 4608u);
        uint32_t db = smem_u32(s_b);
#pragma unroll
        for (int i = tid; i < 1152; i += 256) cp_async16(db + i * 16, srcB + i);
        asm volatile("cp.async.commit_group;");
    }
#pragma unroll
    for (int ci = 0; ci < 16; ci += 2) {
        float v0 = areg[ci], v1 = areg[ci + 1];
        if (AFFINE) {
            int c0 = b * CIN + ci;
            v0 = gamma[c0] * v0 + beta[c0];
            v1 = gamma[c0 + 1] * v1 + beta[c0 + 1];
        }
        *(uint32_t*)(s_a + tid * 48 + ci * 2) =
            pack_h2(__float2half_rn(v0), __float2half_rn(v1));
    }
    if (CHUNKS > 1) {
        const float* inp = inbase + (16 << 8);
#pragma unroll
        for (int ci = 0; ci < 16; ci++) areg[ci] = inp[(ci << 8) + tid];
    }
    asm volatile("cp.async.wait_group 0;");
    __syncthreads();

    for (int ch = 0; ch < CHUNKS; ch++) {
        const int cur = ch & 1;
        const int nxt = cur ^ 1;

        // ---- issue B prefetch for ch+1 ----
        if (ch + 1 < CHUNKS) {
            const uint4* srcB = (const uint4*)(wbuf + (size_t)((ch + 1) * CTILES + ctile) * 4608u);
            uint32_t db = smem_u32(s_b + nxt * 4608);
#pragma unroll
            for (int i = tid; i < 1152; i += 256) cp_async16(db + i * 16, srcB + i);
            asm volatile("cp.async.commit_group;");
        }

        // ---- compute chunk ch from buffers[cur] ----
        const uint32_t sab = sa_base + cur * SA_STRIDE;
        const uint32_t* sb = s_b + cur * 4608;
#pragma unroll
        for (int dy = 0; dy < 3; dy++) {
#pragma unroll
            for (int dx = 0; dx < 3; dx++) {
                const int t = dy * 3 + dx;
                uint2 bw[8];
#pragma unroll
                for (int nt = 0; nt < 8; nt++)
                    bw[nt] = *(const uint2*)(sb + (t * 8 + nt) * 64 + lane * 2);
                const int sx = rowsel + dx - 1;
                const bool colok = (unsigned)sx < 16u;
#pragma unroll
                for (int mt = 0; mt < 2; mt++) {
                    const int y = warp * 2 + mt;
                    const int sy = y + dy - 1;
                    const bool ok = colok && ((unsigned)sy < 16u);
                    const int spix = ok ? (sy * 16 + sx) : 256;
                    const uint32_t addr = sab + (uint32_t)spix * 48u + (uint32_t)khalf * 16u;
                    uint32_t ah[4];
                    ldsm4(ah, addr);
#pragma unroll
                    for (int nt = 0; nt < 8; nt++)
                        mma16816(acc[mt][nt], ah, bw[nt].x, bw[nt].y);
                }
            }
        }

        // ---- convert A(ch+1) into s_a[nxt]; refill areg with A(ch+2) ----
        if (ch + 1 < CHUNKS) {
            char* san = s_a + nxt * SA_STRIDE;
#pragma unroll
            for (int ci = 0; ci < 16; ci += 2) {
                float v0 = areg[ci], v1 = areg[ci + 1];
                if (AFFINE) {
                    int c0 = b * CIN + (ch + 1) * 16 + ci;
                    v0 = gamma[c0] * v0 + beta[c0];
                    v1 = gamma[c0 + 1] * v1 + beta[c0 + 1];
                }
                *(uint32_t*)(san + tid * 48 + ci * 2) =
                    pack_h2(__float2half_rn(v0), __float2half_rn(v1));
            }
            if (ch + 2 < CHUNKS) {
                const float* inp = inbase + ((size_t)(ch + 2) * 16 << 8);
#pragma unroll
                for (int ci = 0; ci < 16; ci++) areg[ci] = inp[(ci << 8) + tid];
            }
            asm volatile("cp.async.wait_group 0;");
        }
        __syncthreads();
    }

    const int g = lane >> 2;
    const int i2 = (lane & 3) * 2;

    if constexpr (QYFUSE) {
        // h = relu(conv+bias); logits_k += sum h * wlin[k]. h never stored.
        float a[4] = {0.f, 0.f, 0.f, 0.f};
#pragma unroll
        for (int nt = 0; nt < 8; nt++) {
            const int co = cout0 + nt * 8 + i2;
            const float bz0 = bias[co];
            const float bz1 = bias[co + 1];
#pragma unroll
            for (int mt = 0; mt < 2; mt++) {
                const int pixa = warp * 32 + mt * 16 + g;
                float v0 = fmaxf(acc[mt][nt][0] + bz0, 0.0f);
                float v1 = fmaxf(acc[mt][nt][1] + bz1, 0.0f);
                float v2 = fmaxf(acc[mt][nt][2] + bz0, 0.0f);
                float v3 = fmaxf(acc[mt][nt][3] + bz1, 0.0f);
#pragma unroll
                for (int k = 0; k < 4; k++) {
                    const float* wk = wlin + (size_t)k * 32768;
                    a[k] += v0 * wk[co * 256 + pixa] + v1 * wk[(co + 1) * 256 + pixa]
                          + v2 * wk[co * 256 + pixa + 8] + v3 * wk[(co + 1) * 256 + pixa + 8];
                }
            }
        }
        float* red = (float*)smem;
        __syncthreads();
#pragma unroll
        for (int k = 0; k < 4; k++) {
            red[tid] = a[k];
            __syncthreads();
            for (int s = 128; s > 0; s >>= 1) {
                if (tid < s) red[tid] += red[tid + s];
                __syncthreads();
            }
            if (tid == 0) atomicAdd(&logits[b * 4 + k], red[0]);
            __syncthreads();
        }
    } else if constexpr (PAIRZ) {
        // qz2 epilogue fused with z: nt<4 = mu channels, nt+4 = lv channels.
        const int base_c = ctile * 32;
#pragma unroll
        for (int nt = 0; nt < 4; nt++) {
#pragma unroll
            for (int mt = 0; mt < 2; mt++) {
#pragma unroll
                for (int j = 0; j < 4; j++) {
                    const int c = base_c + nt * 8 + i2 + (j & 1);
                    const int pix = warp * 32 + mt * 16 + g + ((j >> 1) << 3);
                    float mu = clamp10(acc[mt][nt][j] + bias[c]);
                    float lv = clamp10(acc[mt][nt + 4][j] + bias[c + 128]);
                    float sd = std_from_lv(lv);
                    float lsd = logstd_from_lv(lv);
                    size_t idx = (((size_t)b * 128 + c) << 8) + pix;
                    float e = eps[idx];
                    out[OFF_Z + idx] = mu + sd * e;
                    out[OFF_QMU + idx] = mu;
                    out[OFF_QLV + idx] = lv;
                    out[OFF_LPQ + idx] = -0.5f * e * e - lsd - 0.5f * LOG2PI;
                }
            }
        }
    } else {
        // normal epilogue
#pragma unroll
        for (int nt = 0; nt < 8; nt++) {
            const int co = cout0 + nt * 8 + i2;
            const float bz0 = bias[co];
            const float bz1 = bias[co + 1];
            float* o = out + (((size_t)b * COUT + co) << 8);
#pragma unroll
            for (int mt = 0; mt < 2; mt++) {
                const int pixa = warp * 32 + mt * 16 + g;
                float v0 = acc[mt][nt][0] + bz0;
                float v1 = acc[mt][nt][1] + bz1;
                float v2 = acc[mt][nt][2] + bz0;
                float v3 = acc[mt][nt][3] + bz1;
                if (RELU) {
                    v0 = fmaxf(v0, 0.0f); v1 = fmaxf(v1, 0.0f);
                    v2 = fmaxf(v2, 0.0f); v3 = fmaxf(v3, 0.0f);
                }
                o[pixa] = v0;
                o[256 + pixa] = v1;
                o[pixa + 8] = v2;
                o[256 + pixa + 8] = v3;
            }
        }
    }
}

// ---------------------------------------------------------------------------
// Per-batch small work: gumbel softmax y, cross_entropy, js.
// ---------------------------------------------------------------------------
__global__ __launch_bounds__(256)
void small_kernel(const float* __restrict__ logits, const float* __restrict__ u,
                  const int* __restrict__ label, float* __restrict__ out) {
    const int b = threadIdx.x;
    float l[K_], y[K_];
#pragma unroll
    for (int k = 0; k < K_; k++) l[k] = logits[b * K_ + k];

    float s[K_];
    float mx = -1e30f;
#pragma unroll
    for (int k = 0; k < K_; k++) {
        float uu = u[b * K_ + k];
        float g = -logf(-logf(uu));
        s[k] = l[k] + g;
        mx = fmaxf(mx, s[k]);
    }
    float sum = 0.0f;
#pragma unroll
    for (int k = 0; k < K_; k++) { y[k] = expf(s[k] - mx); sum += y[k]; }
    float inv = 1.0f / sum;
#pragma unroll
    for (int k = 0; k < K_; k++) {
        y[k] *= inv;
        out[OFF_Y + b * K_ + k] = y[k];
    }

    float mx2 = fmaxf(fmaxf(l[0], l[1]), fmaxf(l[2], l[3]));
    float se = 0.0f;
#pragma unroll
    for (int k = 0; k < K_; k++) se += expf(l[k] - mx2);
    float lse = logf(se) + mx2;
    int lbl = label[b];
    float ce_b = lse - l[lbl];

    const float prior = 1.0f / K_;
    float t1 = 0.0f, t2 = 0.0f;
#pragma unroll
    for (int k = 0; k < K_; k++) {
        float m = 0.5f * (y[k] + prior);
        t1 += y[k] * logf(y[k] / (m + 1e-10f));
        t2 += prior * logf(prior / (m + 1e-10f));
    }
    float js_b = 0.5f * t1 + 0.5f * t2;

    __shared__ double r1[256], r2[256];
    r1[b] = (double)ce_b;
    r2[b] = (double)js_b;
    __syncthreads();
    for (int st = 128; st > 0; st >>= 1) {
        if (b < st) { r1[b] += r1[b + st]; r2[b] += r2[b + st]; }
        __syncthreads();
    }
    if (b == 0) {
        out[OFF_CE] = (float)(r1[0] / (double)B_);
        g_js_mean = r2[0] / (double)B_;
        g_kl_sum = 0.0;
    }
}

// ---------------------------------------------------------------------------
// gamma/beta: one block per b, one thread per channel.
// ---------------------------------------------------------------------------
__global__ __launch_bounds__(256)
void gb_kernel(const float* __restrict__ logits,
               const float* __restrict__ gamma_w, const float* __restrict__ gamma_b,
               const float* __restrict__ beta_w, const float* __restrict__ beta_b,
               float* __restrict__ gamma, float* __restrict__ beta) {
    const int b = blockIdx.x;
    const int c = threadIdx.x;
    float l0 = logits[b * K_ + 0], l1 = logits[b * K_ + 1];
    float l2 = logits[b * K_ + 2], l3 = logits[b * K_ + 3];
    float4 gw = ((const float4*)gamma_w)[c];
    float4 bw = ((const float4*)beta_w)[c];
    gamma[b * CIN_ + c] = gw.x * l0 + gw.y * l1 + gw.z * l2 + gw.w * l3 + gamma_b[c];
    beta[b * CIN_ + c]  = bw.x * l0 + bw.y * l1 + bw.z * l2 + bw.w * l3 + beta_b[c];
}

// ---------------------------------------------------------------------------
// logprob_p (layout [b,c,pix,k]) + fused KL(label) reduce (float4 over pix)
// ---------------------------------------------------------------------------
__global__ __launch_bounds__(256)
void pk_kernel(const float* __restrict__ p, const int* __restrict__ label,
               float* __restrict__ out) {
    int idx = blockIdx.x * 256 + threadIdx.x;   // B*CV*HW/4
    int e4 = idx << 2;
    int b = e4 >> 15;
    int r = e4 & 32767;
    int c = r >> 8;
    int pix = r & 255;
    int lbl = label[b];

    float4 z4 = ((const float4*)(out + OFF_Z))[idx];
    float zz[4] = {z4.x, z4.y, z4.z, z4.w};
    float qm[4], qs[4], lqs[4];
    const float* qmu = out + OFF_QMU + e4;
    const float* qlvp = out + OFF_QLV + e4;
#pragma unroll
    for (int j = 0; j < 4; j++) {
        qm[j] = qmu[j];
        float qlv = qlvp[j];
        qs[j] = std_from_lv(qlv);
        lqs[j] = logstd_from_lv(qlv);
    }

    float lp[4][4];
    float klv = 0.0f;
#pragma unroll
    for (int k = 0; k < K_; k++) {
        size_t base = (((size_t)b * (2 * K_ * CV_) + k * CV_ + c) << 8) + pix;
        float4 pm4 = *(const float4*)&p[base];
        float4 pl4 = *(const float4*)&p[base + ((size_t)(K_ * CV_) << 8)];
        float pmv[4] = {pm4.x, pm4.y, pm4.z, pm4.w};
        float plv[4] = {pl4.x, pl4.y, pl4.z, pl4.w};
#pragma unroll
        for (int j = 0; j < 4; j++) {
            float pm = clamp10(pmv[j]);
            float pv = clamp10(plv[j]);
            float ps = std_from_lv(pv);
            float lps = logstd_from_lv(pv);
            float inv_ps = 1.0f / ps;
            float d = (zz[j] - pm) * inv_ps;
            lp[j][k] = -0.5f * d * d - lps - 0.5f * LOG2PI;
            if (k == lbl) {
                float dd = qm[j] - pm;
                klv += lps - lqs[j] +
                       (qs[j] * qs[j] + dd * dd) * (0.5f * inv_ps * inv_ps) - 0.5f;
            }
        }
    }
    float4* lpp = (float4*)(out + OFF_LPP) + (size_t)e4;
#pragma unroll
    for (int j = 0; j < 4; j++)
        lpp[j] = make_float4(lp[j][0], lp[j][1], lp[j][2], lp[j][3]);

    __shared__ float red[256];
    red[threadIdx.x] = klv;
    __syncthreads();
    for (int s = 128; s > 0; s >>= 1) {
        if (threadIdx.x < s) red[threadIdx.x] += red[threadIdx.x + s];
        __syncthreads();
    }
    if (threadIdx.x == 0) atomicAdd(&g_kl_sum, (double)red[0]);
}

__global__ void finalize_kernel(float* __restrict__ out) {
    out[OFF_KLT] = (float)(g_kl_sum / (double)(B_ * CV_ * HW_) + g_js_mean);
}

// ---------------------------------------------------------------------------
// Launch
// ---------------------------------------------------------------------------
extern "C" void kernel_launch(void* const* d_in, const int* in_sizes, int n_in,
                              void* d_out, int out_size) {
    const float* p_params = (const float*)d_in[0];
    const float* q_params = (const float*)d_in[1];
    const int*   label    = (const int*)d_in[2];
    const float* eps      = (const float*)d_in[3];
    const float* u_gumbel = (const float*)d_in[4];
    const float* qy_conv_w = (const float*)d_in[5];
    const float* qy_conv_b = (const float*)d_in[6];
    const float* qy_lin_w  = (const float*)d_in[7];
    const float* qy_lin_b  = (const float*)d_in[8];
    const float* gamma_w   = (const float*)d_in[9];
    const float* gamma_b   = (const float*)d_in[10];
    const float* beta_w    = (const float*)d_in[11];
    const float* beta_b    = (const float*)d_in[12];
    const float* qz1_w     = (const float*)d_in[13];
    const float* qz1_b     = (const float*)d_in[14];
    const float* qz2_w     = (const float*)d_in[15];
    const float* qz2_b     = (const float*)d_in[16];
    const float* out_w     = (const float*)d_in[17];
    const float* out_b     = (const float*)d_in[18];
    float* out = (float*)d_out;

    float *t1, *logits, *gamma, *beta;
    uint32_t* wbuf;
    cudaGetSymbolAddress((void**)&t1, g_t1);
    cudaGetSymbolAddress((void**)&logits, g_logits);
    cudaGetSymbolAddress((void**)&gamma, g_gamma);
    cudaGetSymbolAddress((void**)&beta, g_beta);
    cudaGetSymbolAddress((void**)&wbuf, g_wbuf);

    cudaFuncSetAttribute(conv_mma_kernel<CIN_, CV_, true, false, false, true>,
                         cudaFuncAttributeMaxDynamicSharedMemorySize, CONV_SMEM);
    cudaFuncSetAttribute(conv_mma_kernel<CIN_, 2 * CV_, true, true, false, false>,
                         cudaFuncAttributeMaxDynamicSharedMemorySize, CONV_SMEM);
    cudaFuncSetAttribute(conv_mma_kernel<2 * CV_, 2 * CV_, false, false, true, false>,
                         cudaFuncAttributeMaxDynamicSharedMemorySize, CONV_SMEM);
    cudaFuncSetAttribute(conv_mma_kernel<CV_, COUT_, false, false, false, false>,
                         cudaFuncAttributeMaxDynamicSharedMemorySize, CONV_SMEM);

    cudaStream_t s2;
    cudaStreamCreateWithFlags(&s2, cudaStreamNonBlocking);
    cudaEvent_t evB, evC, evD;
    cudaEventCreateWithFlags(&evB, cudaEventDisableTiming);
    cudaEventCreateWithFlags(&evC, cudaEventDisableTiming);
    cudaEventCreateWithFlags(&evD, cudaEventDisableTiming);

    // 0) logits init (qy conv epilogue atomically accumulates into it)
    logits_init_kernel<<<1, 1024>>>(qy_lin_b, logits);
    // 0b) merged weight prep
    wprep_all_kernel<<<(WBUF_TOTAL + 255) / 256, 256>>>(qy_conv_w, qz1_w, qz2_w, out_w, wbuf);

    // 1) qy conv + fused qy_lin -> logits (h never stored)
    conv_mma_kernel<CIN_, CV_, true, false, false, true><<<dim3(2, B_), 256, CONV_SMEM>>>(
        q_params, wbuf + WOFF_QY, qy_conv_b, nullptr, nullptr, nullptr, qy_lin_w, logits, nullptr);
    cudaEventRecord(evB, 0);

    // s2: small (y/ce/js + kl reset), parallel with gb + qz1
    cudaStreamWaitEvent(s2, evB, 0);
    small_kernel<<<1, 256, 0, s2>>>(logits, u_gumbel, label, out);

    // main: gamma/beta then qz1, qz2
    gb_kernel<<<B_, 256>>>(logits, gamma_w, gamma_b, beta_w, beta_b, gamma, beta);
    conv_mma_kernel<CIN_, 2 * CV_, true, true, false, false><<<dim3(4, B_), 256, CONV_SMEM>>>(
        q_params, wbuf + WOFF_QZ1, qz1_b, t1, gamma, beta, nullptr, nullptr, nullptr);
    conv_mma_kernel<2 * CV_, 2 * CV_, false, false, true, false><<<dim3(4, B_), 256, CONV_SMEM>>>(
        t1, wbuf + WOFF_QZ2, qz2_b, out, nullptr, nullptr, nullptr, nullptr, eps);
    cudaEventRecord(evC, 0);

    // s2: pk (after small in s2 order, after qz2 via evC) || main: out conv
    cudaStreamWaitEvent(s2, evC, 0);
    pk_kernel<<<(B_ * CV_ * HW_) / 1024, 256, 0, s2>>>(p_params, label, out);
    cudaEventRecord(evD, s2);
    conv_mma_kernel<CV_, COUT_, false, false, false, false><<<dim3(4, B_), 256, CONV_SMEM>>>(
        out + OFF_Z, wbuf + WOFF_OUT, out_b, out + OFF_OUT, nullptr, nullptr, nullptr, nullptr, nullptr);
    cudaStreamWaitEvent(0, evD, 0);

    // finalize
    finalize_kernel<<<1, 1>>>(out);

    cudaEventDestroy(evB);
    cudaEventDestroy(evC);
    cudaEventDestroy(evD);
    cudaStreamDestroy(s2);
}